// round 13
// baseline (speedup 1.0000x reference)
#include <cuda_runtime.h>
#include <cuda_bf16.h>
#include <cstdint>

#define NN 50000
#define NE 800000
#define DD 128
#define MAXDEG 128   // Poisson(16) max over 50k nodes ~45; 128 is overwhelmingly safe

// tcgen05 is only legal on arch-specific targets (sm_103a / sm_100a).
// The harness also compiles a plain compute_103 pass -> give it a stub body.
#if !defined(__CUDA_ARCH__) || defined(__CUDA_ARCH_FEAT_SM103_ALL) || \
    defined(__CUDA_ARCH_FEAT_SM100_ALL) || defined(__CUDA_ARCH_SPECIFIC__)
#define TC5 1
#else
#define TC5 0
#endif

// ---------------- scratch (no allocs -> device globals) ----------------
// g_deg must be 0 at entry to k_ph: static-init covers call 1; k_mma<2> re-zeros
// at the end of every call (agg2 is the last reader), keeping the invariant
// across CUDA-graph replays.
__device__ int   g_deg[NN];
__device__ int   g_adj[(size_t)NN * MAXDEG];   // slot table: adj[dst*128 + rank]
__device__ __align__(16) float          g_h1[(size_t)NN * DD];   // fp32 (split at mma load)
__device__ __align__(16) __nv_bfloat16  g_mhi[(size_t)NN * DD];
__device__ __align__(16) __nv_bfloat16  g_mlo[(size_t)NN * DD];
__device__ __align__(16) __nv_bfloat16  g_B1hi[DD * 2 * DD];  // [j][k] k-major, K=256
__device__ __align__(16) __nv_bfloat16  g_B1lo[DD * 2 * DD];
__device__ __align__(16) __nv_bfloat16  g_B2hi[DD * 2 * DD];
__device__ __align__(16) __nv_bfloat16  g_B2lo[DD * 2 * DD];

// ---------------- small helpers ----------------
__device__ __forceinline__ uint32_t s2u32(const void* p) {
    uint32_t a;
    asm("{ .reg .u64 t; cvta.to.shared.u64 t, %1; cvt.u32.u64 %0, t; }" : "=r"(a) : "l"(p));
    return a;
}
__device__ __forceinline__ unsigned pk2(__nv_bfloat16 a, __nv_bfloat16 b) {
    unsigned short ua = *(unsigned short*)&a, ub = *(unsigned short*)&b;
    return (unsigned)ua | ((unsigned)ub << 16);
}
__device__ __forceinline__ void split1(float v, __nv_bfloat16& h, __nv_bfloat16& l) {
    h = __float2bfloat16_rn(v);
    l = __float2bfloat16_rn(v - __bfloat162float(h));
}

// ---------------- fused: weight split | slot-table build (one pass, no CSR) ----------------
#define WPREP_BLOCKS 128
#define HIST_BLOCKS  ((NE + 255) / 256)                // 3125
__global__ void k_ph(const void* __restrict__ ei,
                     const float* __restrict__ W1l, const float* __restrict__ W1r,
                     const float* __restrict__ W2l, const float* __restrict__ W2r) {
    int b = blockIdx.x;
    if (b < WPREP_BLOCKS) {
        int id = b * 256 + threadIdx.x;  // < 32768
        int j = id >> 8, k = id & 255;
        float w1 = (k < DD) ? W1l[j * DD + k] : W1r[j * DD + k - DD];
        float w2 = (k < DD) ? W2l[j * DD + k] : W2r[j * DD + k - DD];
        __nv_bfloat16 h, l;
        split1(w1, h, l); g_B1hi[id] = h; g_B1lo[id] = l;
        split1(w2, h, l); g_B2hi[id] = h; g_B2lo[id] = l;
    } else {
        // local edge-dtype detect (JAX x64-off -> int32 likely). If the buffer is
        // int64, every word is a valid node id < NN. If int32, a 64-bit word holds
        // two ids and is >= 2^32 * id_hi (>= NN unless id_hi == 0, p ~ 2e-5/word).
        const unsigned long long* e64 = (const unsigned long long*)ei;
        bool is32 = false;
        #pragma unroll
        for (int k = 0; k < 8; k++)
            if (e64[k] >= (unsigned long long)NN) is32 = true;
        int e = (b - WPREP_BLOCKS) * 256 + threadIdx.x;
        if (e < NE) {
            int dst = is32 ? ((const int*)ei)[NE + e] : (int)((const long long*)ei)[NE + e];
            int src = is32 ? ((const int*)ei)[e]      : (int)((const long long*)ei)[e];
            if ((unsigned)dst < (unsigned)NN && (unsigned)src < (unsigned)NN) {
                int r = atomicAdd(&g_deg[dst], 1);
                if (r < MAXDEG) g_adj[(size_t)dst * MAXDEG + r] = src;
            }
        }
    }
}

// ---------------- mean aggregation: one warp per node; fp32 in, bf16 hi/lo out ----------------
// LAYER selects the feature source ON DEVICE (x param vs g_h1 symbol).
// 8-deep load batching (16 LDG.128 in flight per thread-pair of chains) + 4
// independent f32x2 accumulator chains -> latency-bound gather gets MLP ~8.
template <int LAYER>
__global__ void __launch_bounds__(256) k_agg(const float* __restrict__ x) {
    const float* feat = (LAYER == 1) ? x : (const float*)g_h1;
    int warp = (blockIdx.x * blockDim.x + threadIdx.x) >> 5;
    int lane = threadIdx.x & 31;
    if (warp >= NN) return;
    const int* adjrow = g_adj + (size_t)warp * MAXDEG;
    int d = min(g_deg[warp], MAXDEG);
    unsigned long long acc[4] = {0ULL, 0ULL, 0ULL, 0ULL};   // [0],[1]: cols 0-1/2-3 chainA; [2],[3]: chainB
    for (int b = 0; b < d; b += 32) {
        int m  = min(32, d - b);
        int sl = (lane < m) ? adjrow[b + lane] : 0;
        int j = 0;
        for (; j + 8 <= m; j += 8) {
            ulonglong2 v[8];
            #pragma unroll
            for (int q = 0; q < 8; q++) {
                int s = __shfl_sync(0xffffffffu, sl, j + q);
                v[q] = __ldg((const ulonglong2*)(feat + (size_t)s * DD) + lane);
            }
            #pragma unroll
            for (int q = 0; q < 8; q++) {
                int c = (q & 1) << 1;   // alternate chain A/B
                asm("add.rn.f32x2 %0, %0, %1;" : "+l"(acc[c])     : "l"(v[q].x));
                asm("add.rn.f32x2 %0, %0, %1;" : "+l"(acc[c + 1]) : "l"(v[q].y));
            }
        }
        for (; j < m; j++) {
            int s = __shfl_sync(0xffffffffu, sl, j);
            ulonglong2 v = __ldg((const ulonglong2*)(feat + (size_t)s * DD) + lane);
            int c = (j & 1) << 1;
            asm("add.rn.f32x2 %0, %0, %1;" : "+l"(acc[c])     : "l"(v.x));
            asm("add.rn.f32x2 %0, %0, %1;" : "+l"(acc[c + 1]) : "l"(v.y));
        }
    }
    // merge chains
    asm("add.rn.f32x2 %0, %0, %1;" : "+l"(acc[0]) : "l"(acc[2]));
    asm("add.rn.f32x2 %0, %0, %1;" : "+l"(acc[1]) : "l"(acc[3]));
    float inv = 1.0f / (float)max(d, 1);
    float f0, f1, f2, f3;
    asm("mov.b64 {%0, %1}, %2;" : "=f"(f0), "=f"(f1) : "l"(acc[0]));
    asm("mov.b64 {%0, %1}, %2;" : "=f"(f2), "=f"(f3) : "l"(acc[1]));
    f0 *= inv; f1 *= inv; f2 *= inv; f3 *= inv;
    __nv_bfloat16 h0, h1, h2, h3, l0, l1, l2, l3;
    split1(f0, h0, l0); split1(f1, h1, l1);
    split1(f2, h2, l2); split1(f3, h3, l3);
    size_t rb = (size_t)warp * DD;
    ((uint2*)(g_mhi + rb))[lane] = make_uint2(pk2(h0, h1), pk2(h2, h3));
    ((uint2*)(g_mlo + rb))[lane] = make_uint2(pk2(l0, l1), pk2(l2, l3));
}

// ================= tcgen05 GEMM =================
// Per CTA: 128 rows, N=128, K=256. SS bf16 MMA, fp32 TMEM accum.
// D = Ahi*Bhi + Alo*Bhi + Ahi*Blo  (2-way bf16 split of fp32)
// smem: [1KB slack] A_hi 64KB | A_lo 64KB | B 64KB (Bhi, then Blo via reg preload).
// A left half (cols 0..127) = mean bf16 hi/lo via cp.async.
// A right half (cols 128..255) = fp32 features (x / g_h1) split in registers.
// Layer 1 epilogue writes fp32 h1; layer 2 fuses LayerNorm + re-zeros g_deg.

#define SM_AHI 0
#define SM_ALO 65536
#define SM_B   131072
#define DSMEM  (196608 + 1024)

static constexpr uint32_t IDESC_BF16 =
    (1u << 4) | (1u << 7) | (1u << 10) | ((128u / 8) << 17) | ((128u / 16) << 24);

// blocked SW128 atom layout: atom = 8 rows x 64 bf16 (1024B); 16 atom-rows, 4 atom-cols
__device__ __forceinline__ int sw_chunk(int row, int col) {   // col multiple of 8
    int byte = ((row >> 3) + (col >> 6) * 16) * 1024 + (row & 7) * 128 + (col & 63) * 2;
    return byte ^ ((byte >> 3) & 0x70);
}
__device__ __forceinline__ uint64_t mk_desc(uint32_t addr) {
    const uint64_t base = (2ull << 61) | (1ull << 46) | (64ull << 32) | (1ull << 16);
    return base | ((uint64_t)(addr >> 4) & 0x3FFF);
}
__device__ __forceinline__ uint64_t koff(int t) {   // K16-step t=0..15
    return (uint64_t)(((t >> 2) * 1024) + (t & 3) * 2);
}

#if TC5
__device__ __forceinline__ void mma_bf16_ss(uint32_t d, uint64_t ad, uint64_t bd,
                                            uint32_t en) {
    asm volatile(
        "{\n\t.reg .pred p;\n\tsetp.ne.u32 p, %4, 0;\n\t"
        "tcgen05.mma.cta_group::1.kind::f16 [%0], %1, %2, %3, {%5, %5, %5, %5}, p;\n\t}"
        :: "r"(d), "l"(ad), "l"(bd), "r"(IDESC_BF16), "r"(en), "r"(0u) : "memory");
}
__device__ __forceinline__ void cp16(uint32_t saddr, const void* gaddr) {
    asm volatile("cp.async.cg.shared.global [%0], [%1], 16;"
                 :: "r"(saddr), "l"(gaddr) : "memory");
}
#endif
__device__ __forceinline__ void mbar_wait(uint32_t mbar, uint32_t parity) {
    uint32_t done;
    asm volatile(
        "{\n\t.reg .pred p;\n\t"
        "mbarrier.try_wait.parity.acquire.cta.shared::cta.b64 p, [%1], %2;\n\t"
        "selp.b32 %0, 1, 0, p;\n\t}"
        : "=r"(done) : "r"(mbar), "r"(parity) : "memory");
    if (!done) {
        asm volatile(
            "{\n\t.reg .pred P1;\n\t"
            "WL_%=:\n\t"
            "mbarrier.try_wait.parity.acquire.cta.shared::cta.b64 P1, [%0], %1, 0x989680;\n\t"
            "@P1 bra.uni WD_%=;\n\t"
            "bra.uni WL_%=;\n\t"
            "WD_%=:\n\t}"
            :: "r"(mbar), "r"(parity) : "memory");
    }
}

template <int LAYER>
__global__ void __launch_bounds__(256) k_mma(
    const float* __restrict__ xin, const float* __restrict__ bias,
    const float* __restrict__ lnw, const float* __restrict__ lnb,
    float* __restrict__ outp)
{
#if TC5
    extern __shared__ char dsm_raw[];
    __shared__ uint32_t s_tmem;
    __shared__ __align__(8) unsigned long long s_mbar;
    __shared__ float sb[DD], slw[DD], slb[DD];
    __shared__ float psS[2][DD], psQ[2][DD];

    const uint32_t raw_u = s2u32(dsm_raw);
    const uint32_t dsm_u = (raw_u + 1023u) & ~1023u;   // SW128 needs 1KB-aligned base
    char* dsm = dsm_raw + (dsm_u - raw_u);

    const int tid  = threadIdx.x;
    const int wid  = tid >> 5;
    const int lane = tid & 31;
    const int row0 = blockIdx.x * 128;

    const float* hsrc = (LAYER == 1) ? xin : (const float*)g_h1;
    const __nv_bfloat16* Bhi = (LAYER == 1) ? g_B1hi : g_B2hi;
    const __nv_bfloat16* Blo = (LAYER == 1) ? g_B1lo : g_B2lo;

    uint32_t mbar_a = s2u32(&s_mbar);
    uint32_t tmslot = s2u32(&s_tmem);

    if (wid == 0) {
        asm volatile(
            "tcgen05.alloc.cta_group::1.sync.aligned.shared::cta.b32 [%0], %1;"
            :: "r"(tmslot), "r"(128u) : "memory");
    }
    if (tid == 0)
        asm volatile("mbarrier.init.shared.b64 [%0], %1;" :: "r"(mbar_a), "r"(1u) : "memory");
    if (tid < DD) {
        sb[tid] = bias[tid];
        if (LAYER == 2) { slw[tid] = lnw[tid]; slb[tid] = lnb[tid]; }
    }

    // Layer 2: re-zero g_deg for the next call (agg2 was the last reader; this
    // kernel is stream-ordered after it). Grid 391*256 covers NN.
    if (LAYER == 2) {
        int zi = blockIdx.x * 256 + tid;
        if (zi < NN) g_deg[zi] = 0;
    }

    // ---- chunk map: 16 chunks/thread of 16B; row=c>>5, col=(c&31)*8 ----
    int rr[16], cc[16], so[16];
    #pragma unroll
    for (int it = 0; it < 16; it++) {
        int c = tid + it * 256;
        rr[it] = c >> 5; cc[it] = (c & 31) * 8;
        so[it] = sw_chunk(rr[it], cc[it]);
    }

    // group 1: B(hi) + mean-hi (left half)
    #pragma unroll
    for (int it = 0; it < 16; it++)
        cp16(dsm_u + SM_B + so[it], Bhi + rr[it] * 256 + cc[it]);
    #pragma unroll
    for (int it = 0; it < 16; it++) {
        if (cc[it] < DD) {
            int gr = row0 + rr[it]; if (gr >= NN) gr = 0;   // clamp: rows never stored
            cp16(dsm_u + SM_AHI + so[it], g_mhi + (size_t)gr * DD + cc[it]);
        }
    }
    asm volatile("cp.async.commit_group;" ::: "memory");     // group: B + mean-hi
    #pragma unroll
    for (int it = 0; it < 16; it++) {
        if (cc[it] < DD) {
            int gr = row0 + rr[it]; if (gr >= NN) gr = 0;
            cp16(dsm_u + SM_ALO + so[it], g_mlo + (size_t)gr * DD + cc[it]);
        }
    }
    asm volatile("cp.async.commit_group;" ::: "memory");     // group: mean-lo

    // right half: fp32 features, split in registers, STS to both buffers
    #pragma unroll
    for (int it = 0; it < 16; it++) {
        if (cc[it] >= DD) {
            int gr = row0 + rr[it]; if (gr >= NN) gr = 0;
            const float* xr = hsrc + (size_t)gr * DD + (cc[it] - DD);
            float4 a = *(const float4*)xr;
            float4 b = *(const float4*)(xr + 4);
            __nv_bfloat16 h[8], l[8];
            split1(a.x, h[0], l[0]); split1(a.y, h[1], l[1]);
            split1(a.z, h[2], l[2]); split1(a.w, h[3], l[3]);
            split1(b.x, h[4], l[4]); split1(b.y, h[5], l[5]);
            split1(b.z, h[6], l[6]); split1(b.w, h[7], l[7]);
            *(uint4*)(dsm + SM_AHI + so[it]) =
                make_uint4(pk2(h[0],h[1]), pk2(h[2],h[3]), pk2(h[4],h[5]), pk2(h[6],h[7]));
            *(uint4*)(dsm + SM_ALO + so[it]) =
                make_uint4(pk2(l[0],l[1]), pk2(l[2],l[3]), pk2(l[4],l[5]), pk2(l[6],l[7]));
        }
    }

    __syncthreads();   // alloc + mbar init visible
    uint32_t tmem;
    asm volatile("ld.shared.b32 %0, [%1];" : "=r"(tmem) : "r"(tmslot));

    uint64_t dAhi = mk_desc(dsm_u + SM_AHI);
    uint64_t dAlo = mk_desc(dsm_u + SM_ALO);
    uint64_t dB   = mk_desc(dsm_u + SM_B);

    // ---- phase A1: Ahi*Bhi (mean-lo may still be streaming) ----
    asm volatile("cp.async.wait_group 1;" ::: "memory");
    __syncthreads();
    if (tid == 0) {
        asm volatile("fence.proxy.async.shared::cta;" ::: "memory");
        #pragma unroll
        for (int t = 0; t < 16; t++)
            mma_bf16_ss(tmem, dAhi + koff(t), dB + koff(t), t > 0);
    }
    // ---- phase A2: Alo*Bhi ----
    asm volatile("cp.async.wait_group 0;" ::: "memory");
    __syncthreads();
    if (tid == 0) {
        asm volatile("fence.proxy.async.shared::cta;" ::: "memory");
        #pragma unroll
        for (int t = 0; t < 16; t++)
            mma_bf16_ss(tmem, dAlo + koff(t), dB + koff(t), 1);
        asm volatile(
            "tcgen05.commit.cta_group::1.mbarrier::arrive::one.shared::cluster.b64 [%0];"
            :: "r"(mbar_a) : "memory");
    }

    // ---- preload Blo into registers under the phase-A shadow ----
    uint4 bl[16];
    #pragma unroll
    for (int it = 0; it < 16; it++)
        bl[it] = *(const uint4*)(Blo + rr[it] * 256 + cc[it]);

    mbar_wait(mbar_a, 0);

    // ---- swap B -> Blo (STS only) ----
    #pragma unroll
    for (int it = 0; it < 16; it++)
        *(uint4*)(dsm + SM_B + so[it]) = bl[it];
    __syncthreads();

    // ---- phase B: Ahi*Blo ----
    if (tid == 0) {
        asm volatile("fence.proxy.async.shared::cta;" ::: "memory");
        #pragma unroll
        for (int t = 0; t < 16; t++)
            mma_bf16_ss(tmem, dAhi + koff(t), dB + koff(t), 1);
        asm volatile(
            "tcgen05.commit.cta_group::1.mbarrier::arrive::one.shared::cluster.b64 [%0];"
            :: "r"(mbar_a) : "memory");
    }
    mbar_wait(mbar_a, 1);
    asm volatile("tcgen05.fence::after_thread_sync;" ::: "memory");

    // ---- epilogue: warp w -> rows (w&3)*32+lane, cols (w>>2)*64..+63 ----
    const int sub = wid & 3, half = wid >> 2;
    const int cb = half * 64;
    uint32_t dr[64];
    #define LD32(p, a) \
        asm volatile("tcgen05.ld.sync.aligned.32x32b.x32.b32 " \
            "{%0,%1,%2,%3,%4,%5,%6,%7,%8,%9,%10,%11,%12,%13,%14,%15," \
            "%16,%17,%18,%19,%20,%21,%22,%23,%24,%25,%26,%27,%28,%29,%30,%31}, [%32];" \
            : "=r"((p)[0]),"=r"((p)[1]),"=r"((p)[2]),"=r"((p)[3]),"=r"((p)[4]),"=r"((p)[5]), \
              "=r"((p)[6]),"=r"((p)[7]),"=r"((p)[8]),"=r"((p)[9]),"=r"((p)[10]),"=r"((p)[11]), \
              "=r"((p)[12]),"=r"((p)[13]),"=r"((p)[14]),"=r"((p)[15]),"=r"((p)[16]),"=r"((p)[17]), \
              "=r"((p)[18]),"=r"((p)[19]),"=r"((p)[20]),"=r"((p)[21]),"=r"((p)[22]),"=r"((p)[23]), \
              "=r"((p)[24]),"=r"((p)[25]),"=r"((p)[26]),"=r"((p)[27]),"=r"((p)[28]),"=r"((p)[29]), \
              "=r"((p)[30]),"=r"((p)[31]) : "r"(a))
    LD32(dr,      tmem + cb);
    LD32(dr + 32, tmem + cb + 32);
    asm volatile("tcgen05.wait::ld.sync.aligned;" ::: "memory");
    #undef LD32

    const int r = sub * 32 + lane;          // local row
    const int gr = row0 + r;
    float v[64];
    float s = 0.f, sq = 0.f;
    #pragma unroll
    for (int j = 0; j < 64; j++) {
        float f = fmaxf(__uint_as_float(dr[j]) + sb[cb + j], 0.f);
        v[j] = f;
        s += f; sq += f * f;
    }

    if (LAYER == 1) {
        if (gr < NN) {
            size_t rbase = (size_t)gr * DD + cb;
            #pragma unroll
            for (int c4 = 0; c4 < 16; c4++)
                *(float4*)(g_h1 + rbase + c4 * 4) =
                    make_float4(v[c4*4+0], v[c4*4+1], v[c4*4+2], v[c4*4+3]);
        }
    } else {
        psS[half][r] = s;
        psQ[half][r] = sq;
        __syncthreads();
        float st = psS[0][r] + psS[1][r];
        float qt = psQ[0][r] + psQ[1][r];
        float mu  = st * (1.0f / DD);
        float var = qt * (1.0f / DD) - mu * mu;
        float rs  = rsqrtf(var + 1e-5f);
        if (gr < NN) {
            size_t rbase = (size_t)gr * DD + cb;
            #pragma unroll
            for (int c4 = 0; c4 < 16; c4++) {
                float4 o;
                o.x = (v[c4*4+0] - mu) * rs * slw[cb+c4*4+0] + slb[cb+c4*4+0];
                o.y = (v[c4*4+1] - mu) * rs * slw[cb+c4*4+1] + slb[cb+c4*4+1];
                o.z = (v[c4*4+2] - mu) * rs * slw[cb+c4*4+2] + slb[cb+c4*4+2];
                o.w = (v[c4*4+3] - mu) * rs * slw[cb+c4*4+3] + slb[cb+c4*4+3];
                *(float4*)(outp + rbase + c4 * 4) = o;
            }
        }
    }

    __syncthreads();
    if (tid == 0)
        asm volatile("mbarrier.inval.shared.b64 [%0];" :: "r"(mbar_a) : "memory");
    __syncthreads();
    if (wid == 0) {
        asm volatile("tcgen05.dealloc.cta_group::1.sync.aligned.b32 %0, %1;"
                     :: "r"(tmem), "r"(128u));
        asm volatile("tcgen05.relinquish_alloc_permit.cta_group::1.sync.aligned;");
    }
#endif  // TC5
}

// ---------------- launch ----------------
extern "C" void kernel_launch(void* const* d_in, const int* in_sizes, int n_in,
                              void* d_out, int out_size) {
    const float* x   = (const float*)d_in[0];
    const void*  ei  = d_in[1];
    const float* W1l = (const float*)d_in[2];
    const float* b1l = (const float*)d_in[3];
    const float* W1r = (const float*)d_in[4];
    const float* W2l = (const float*)d_in[5];
    const float* b2l = (const float*)d_in[6];
    const float* W2r = (const float*)d_in[7];
    const float* lnw = (const float*)d_in[8];
    const float* lnb = (const float*)d_in[9];
    float* out = (float*)d_out;

    cudaFuncSetAttribute(k_mma<1>, cudaFuncAttributeMaxDynamicSharedMemorySize, DSMEM);
    cudaFuncSetAttribute(k_mma<2>, cudaFuncAttributeMaxDynamicSharedMemorySize, DSMEM);

    const int ph_blocks  = WPREP_BLOCKS + HIST_BLOCKS;
    const int mma_blocks = (NN + 127) / 128;                    // 391

    // single-pass adjacency build (slot table, no CSR)
    k_ph<<<ph_blocks, 256>>>(ei, W1l, W1r, W2l, W2r);

    // layer 1
    k_agg<1><<<(NN * 32 + 255) / 256, 256>>>(x);
    k_mma<1><<<mma_blocks, 256, DSMEM>>>(x, b1l, nullptr, nullptr, out);

    // layer 2 (+ LayerNorm; re-zeros g_deg for next call)
    k_agg<2><<<(NN * 32 + 255) / 256, 256>>>(x);
    k_mma<2><<<mma_blocks, 256, DSMEM>>>(x, b2l, lnw, lnb, out);
}

// round 14
// speedup vs baseline: 1.2929x; 1.2929x over previous
#include <cuda_runtime.h>
#include <cuda_bf16.h>
#include <cstdint>

#define NN 50000
#define NE 800000
#define DD 128
#define MAXDEG 128   // Poisson(16) max over 50k nodes ~45; 128 is overwhelmingly safe

// tcgen05 is only legal on arch-specific targets (sm_103a / sm_100a).
// The harness also compiles a plain compute_103 pass -> give it a stub body.
#if !defined(__CUDA_ARCH__) || defined(__CUDA_ARCH_FEAT_SM103_ALL) || \
    defined(__CUDA_ARCH_FEAT_SM100_ALL) || defined(__CUDA_ARCH_SPECIFIC__)
#define TC5 1
#else
#define TC5 0
#endif

// ---------------- scratch (no allocs -> device globals) ----------------
// g_deg must be 0 at entry to k_ph: static-init covers call 1; k_mma<2> re-zeros
// at the end of every call (agg2 is the last reader), keeping the invariant
// across CUDA-graph replays.
__device__ int   g_deg[NN];
__device__ int   g_adj[(size_t)NN * MAXDEG];   // slot table: adj[dst*128 + rank]
__device__ __align__(16) float          g_h1[(size_t)NN * DD];   // fp32 (split at mma load)
__device__ __align__(16) __nv_bfloat16  g_mhi[(size_t)NN * DD];
__device__ __align__(16) __nv_bfloat16  g_mlo[(size_t)NN * DD];
__device__ __align__(16) __nv_bfloat16  g_B1hi[DD * 2 * DD];  // [j][k] k-major, K=256
__device__ __align__(16) __nv_bfloat16  g_B1lo[DD * 2 * DD];
__device__ __align__(16) __nv_bfloat16  g_B2hi[DD * 2 * DD];
__device__ __align__(16) __nv_bfloat16  g_B2lo[DD * 2 * DD];

// ---------------- small helpers ----------------
__device__ __forceinline__ uint32_t s2u32(const void* p) {
    uint32_t a;
    asm("{ .reg .u64 t; cvta.to.shared.u64 t, %1; cvt.u32.u64 %0, t; }" : "=r"(a) : "l"(p));
    return a;
}
__device__ __forceinline__ unsigned pk2(__nv_bfloat16 a, __nv_bfloat16 b) {
    unsigned short ua = *(unsigned short*)&a, ub = *(unsigned short*)&b;
    return (unsigned)ua | ((unsigned)ub << 16);
}
__device__ __forceinline__ void split1(float v, __nv_bfloat16& h, __nv_bfloat16& l) {
    h = __float2bfloat16_rn(v);
    l = __float2bfloat16_rn(v - __bfloat162float(h));
}

// ---------------- fused: weight split | slot-table build (one pass, no CSR) ----------------
#define WPREP_BLOCKS 128
#define HIST_BLOCKS  ((NE + 255) / 256)                // 3125
__global__ void k_ph(const void* __restrict__ ei,
                     const float* __restrict__ W1l, const float* __restrict__ W1r,
                     const float* __restrict__ W2l, const float* __restrict__ W2r) {
    int b = blockIdx.x;
    if (b < WPREP_BLOCKS) {
        int id = b * 256 + threadIdx.x;  // < 32768
        int j = id >> 8, k = id & 255;
        float w1 = (k < DD) ? W1l[j * DD + k] : W1r[j * DD + k - DD];
        float w2 = (k < DD) ? W2l[j * DD + k] : W2r[j * DD + k - DD];
        __nv_bfloat16 h, l;
        split1(w1, h, l); g_B1hi[id] = h; g_B1lo[id] = l;
        split1(w2, h, l); g_B2hi[id] = h; g_B2lo[id] = l;
    } else {
        // local edge-dtype detect (JAX x64-off -> int32 likely). If the buffer is
        // int64, every word is a valid node id < NN. If int32, a 64-bit word holds
        // two ids and is >= 2^32 * id_hi (>= NN unless id_hi == 0, p ~ 2e-5/word).
        const unsigned long long* e64 = (const unsigned long long*)ei;
        bool is32 = false;
        #pragma unroll
        for (int k = 0; k < 8; k++)
            if (e64[k] >= (unsigned long long)NN) is32 = true;
        int e = (b - WPREP_BLOCKS) * 256 + threadIdx.x;
        if (e < NE) {
            int dst = is32 ? ((const int*)ei)[NE + e] : (int)((const long long*)ei)[NE + e];
            int src = is32 ? ((const int*)ei)[e]      : (int)((const long long*)ei)[e];
            if ((unsigned)dst < (unsigned)NN && (unsigned)src < (unsigned)NN) {
                int r = atomicAdd(&g_deg[dst], 1);
                if (r < MAXDEG) g_adj[(size_t)dst * MAXDEG + r] = src;
            }
        }
    }
}

// ---------------- mean aggregation: one warp per node; fp32 in, bf16 hi/lo out ----------------
// LAYER selects the feature source ON DEVICE (x param vs g_h1 symbol).
// R12 form: unroll-4 inner loop, 2 f32x2 accumulator chains, regs=32, occ~84%.
// This is AT the chip L2 throughput cap (~410MB / ~32us) -- do not add staging.
template <int LAYER>
__global__ void __launch_bounds__(256) k_agg(const float* __restrict__ x) {
    const float* feat = (LAYER == 1) ? x : (const float*)g_h1;
    int warp = (blockIdx.x * blockDim.x + threadIdx.x) >> 5;
    int lane = threadIdx.x & 31;
    if (warp >= NN) return;
    const int* adjrow = g_adj + (size_t)warp * MAXDEG;
    int d = min(g_deg[warp], MAXDEG);
    unsigned long long a01 = 0ULL, a23 = 0ULL;   // packed f32x2 accumulators
    for (int b = 0; b < d; b += 32) {
        int m  = min(32, d - b);
        int sl = (lane < m) ? adjrow[b + lane] : 0;
        #pragma unroll 4
        for (int j = 0; j < m; j++) {
            int s = __shfl_sync(0xffffffffu, sl, j);
            const ulonglong2 v = __ldg((const ulonglong2*)(feat + (size_t)s * DD) + lane);
            asm("add.rn.f32x2 %0, %0, %1;" : "+l"(a01) : "l"(v.x));
            asm("add.rn.f32x2 %0, %0, %1;" : "+l"(a23) : "l"(v.y));
        }
    }
    float inv = 1.0f / (float)max(d, 1);
    float f0, f1, f2, f3;
    asm("mov.b64 {%0, %1}, %2;" : "=f"(f0), "=f"(f1) : "l"(a01));
    asm("mov.b64 {%0, %1}, %2;" : "=f"(f2), "=f"(f3) : "l"(a23));
    f0 *= inv; f1 *= inv; f2 *= inv; f3 *= inv;
    __nv_bfloat16 h0, h1, h2, h3, l0, l1, l2, l3;
    split1(f0, h0, l0); split1(f1, h1, l1);
    split1(f2, h2, l2); split1(f3, h3, l3);
    size_t rb = (size_t)warp * DD;
    ((uint2*)(g_mhi + rb))[lane] = make_uint2(pk2(h0, h1), pk2(h2, h3));
    ((uint2*)(g_mlo + rb))[lane] = make_uint2(pk2(l0, l1), pk2(l2, l3));
}

// ================= tcgen05 GEMM =================
// Per CTA: 128 rows, N=128, K=256. SS bf16 MMA, fp32 TMEM accum.
// D = Ahi*Bhi + Alo*Bhi + Ahi*Blo  (2-way bf16 split of fp32)
// smem: [1KB slack] A_hi 64KB | A_lo 64KB | B 64KB (Bhi, then Blo via reg preload).
// A left half (cols 0..127) = mean bf16 hi/lo via cp.async.
// A right half (cols 128..255) = fp32 features (x / g_h1) split in registers.
// Layer 1 epilogue writes fp32 h1; layer 2 fuses LayerNorm + re-zeros g_deg.

#define SM_AHI 0
#define SM_ALO 65536
#define SM_B   131072
#define DSMEM  (196608 + 1024)

static constexpr uint32_t IDESC_BF16 =
    (1u << 4) | (1u << 7) | (1u << 10) | ((128u / 8) << 17) | ((128u / 16) << 24);

// blocked SW128 atom layout: atom = 8 rows x 64 bf16 (1024B); 16 atom-rows, 4 atom-cols
__device__ __forceinline__ int sw_chunk(int row, int col) {   // col multiple of 8
    int byte = ((row >> 3) + (col >> 6) * 16) * 1024 + (row & 7) * 128 + (col & 63) * 2;
    return byte ^ ((byte >> 3) & 0x70);
}
__device__ __forceinline__ uint64_t mk_desc(uint32_t addr) {
    const uint64_t base = (2ull << 61) | (1ull << 46) | (64ull << 32) | (1ull << 16);
    return base | ((uint64_t)(addr >> 4) & 0x3FFF);
}
__device__ __forceinline__ uint64_t koff(int t) {   // K16-step t=0..15
    return (uint64_t)(((t >> 2) * 1024) + (t & 3) * 2);
}

#if TC5
__device__ __forceinline__ void mma_bf16_ss(uint32_t d, uint64_t ad, uint64_t bd,
                                            uint32_t en) {
    asm volatile(
        "{\n\t.reg .pred p;\n\tsetp.ne.u32 p, %4, 0;\n\t"
        "tcgen05.mma.cta_group::1.kind::f16 [%0], %1, %2, %3, {%5, %5, %5, %5}, p;\n\t}"
        :: "r"(d), "l"(ad), "l"(bd), "r"(IDESC_BF16), "r"(en), "r"(0u) : "memory");
}
__device__ __forceinline__ void cp16(uint32_t saddr, const void* gaddr) {
    asm volatile("cp.async.cg.shared.global [%0], [%1], 16;"
                 :: "r"(saddr), "l"(gaddr) : "memory");
}
#endif
__device__ __forceinline__ void mbar_wait(uint32_t mbar, uint32_t parity) {
    uint32_t done;
    asm volatile(
        "{\n\t.reg .pred p;\n\t"
        "mbarrier.try_wait.parity.acquire.cta.shared::cta.b64 p, [%1], %2;\n\t"
        "selp.b32 %0, 1, 0, p;\n\t}"
        : "=r"(done) : "r"(mbar), "r"(parity) : "memory");
    if (!done) {
        asm volatile(
            "{\n\t.reg .pred P1;\n\t"
            "WL_%=:\n\t"
            "mbarrier.try_wait.parity.acquire.cta.shared::cta.b64 P1, [%0], %1, 0x989680;\n\t"
            "@P1 bra.uni WD_%=;\n\t"
            "bra.uni WL_%=;\n\t"
            "WD_%=:\n\t}"
            :: "r"(mbar), "r"(parity) : "memory");
    }
}

template <int LAYER>
__global__ void __launch_bounds__(256) k_mma(
    const float* __restrict__ xin, const float* __restrict__ bias,
    const float* __restrict__ lnw, const float* __restrict__ lnb,
    float* __restrict__ outp)
{
#if TC5
    extern __shared__ char dsm_raw[];
    __shared__ uint32_t s_tmem;
    __shared__ __align__(8) unsigned long long s_mbar;
    __shared__ float sb[DD], slw[DD], slb[DD];
    __shared__ float psS[2][DD], psQ[2][DD];

    const uint32_t raw_u = s2u32(dsm_raw);
    const uint32_t dsm_u = (raw_u + 1023u) & ~1023u;   // SW128 needs 1KB-aligned base
    char* dsm = dsm_raw + (dsm_u - raw_u);

    const int tid  = threadIdx.x;
    const int wid  = tid >> 5;
    const int lane = tid & 31;
    const int row0 = blockIdx.x * 128;

    const float* hsrc = (LAYER == 1) ? xin : (const float*)g_h1;
    const __nv_bfloat16* Bhi = (LAYER == 1) ? g_B1hi : g_B2hi;
    const __nv_bfloat16* Blo = (LAYER == 1) ? g_B1lo : g_B2lo;

    uint32_t mbar_a = s2u32(&s_mbar);
    uint32_t tmslot = s2u32(&s_tmem);

    if (wid == 0) {
        asm volatile(
            "tcgen05.alloc.cta_group::1.sync.aligned.shared::cta.b32 [%0], %1;"
            :: "r"(tmslot), "r"(128u) : "memory");
    }
    if (tid == 0)
        asm volatile("mbarrier.init.shared.b64 [%0], %1;" :: "r"(mbar_a), "r"(1u) : "memory");
    if (tid < DD) {
        sb[tid] = bias[tid];
        if (LAYER == 2) { slw[tid] = lnw[tid]; slb[tid] = lnb[tid]; }
    }

    // ---- chunk map: 16 chunks/thread of 16B; row=c>>5, col=(c&31)*8 ----
    int rr[16], cc[16], so[16];
    #pragma unroll
    for (int it = 0; it < 16; it++) {
        int c = tid + it * 256;
        rr[it] = c >> 5; cc[it] = (c & 31) * 8;
        so[it] = sw_chunk(rr[it], cc[it]);
    }

    // group 1: B(hi) + mean-hi (left half)
    #pragma unroll
    for (int it = 0; it < 16; it++)
        cp16(dsm_u + SM_B + so[it], Bhi + rr[it] * 256 + cc[it]);
    #pragma unroll
    for (int it = 0; it < 16; it++) {
        if (cc[it] < DD) {
            int gr = row0 + rr[it]; if (gr >= NN) gr = 0;   // clamp: rows never stored
            cp16(dsm_u + SM_AHI + so[it], g_mhi + (size_t)gr * DD + cc[it]);
        }
    }
    asm volatile("cp.async.commit_group;" ::: "memory");     // group: B + mean-hi
    #pragma unroll
    for (int it = 0; it < 16; it++) {
        if (cc[it] < DD) {
            int gr = row0 + rr[it]; if (gr >= NN) gr = 0;
            cp16(dsm_u + SM_ALO + so[it], g_mlo + (size_t)gr * DD + cc[it]);
        }
    }
    asm volatile("cp.async.commit_group;" ::: "memory");     // group: mean-lo

    // right half: fp32 features, split in registers, STS to both buffers
    #pragma unroll
    for (int it = 0; it < 16; it++) {
        if (cc[it] >= DD) {
            int gr = row0 + rr[it]; if (gr >= NN) gr = 0;
            const float* xr = hsrc + (size_t)gr * DD + (cc[it] - DD);
            float4 a = *(const float4*)xr;
            float4 b = *(const float4*)(xr + 4);
            __nv_bfloat16 h[8], l[8];
            split1(a.x, h[0], l[0]); split1(a.y, h[1], l[1]);
            split1(a.z, h[2], l[2]); split1(a.w, h[3], l[3]);
            split1(b.x, h[4], l[4]); split1(b.y, h[5], l[5]);
            split1(b.z, h[6], l[6]); split1(b.w, h[7], l[7]);
            *(uint4*)(dsm + SM_AHI + so[it]) =
                make_uint4(pk2(h[0],h[1]), pk2(h[2],h[3]), pk2(h[4],h[5]), pk2(h[6],h[7]));
            *(uint4*)(dsm + SM_ALO + so[it]) =
                make_uint4(pk2(l[0],l[1]), pk2(l[2],l[3]), pk2(l[4],l[5]), pk2(l[6],l[7]));
        }
    }

    __syncthreads();   // alloc + mbar init visible
    uint32_t tmem;
    asm volatile("ld.shared.b32 %0, [%1];" : "=r"(tmem) : "r"(tmslot));

    uint64_t dAhi = mk_desc(dsm_u + SM_AHI);
    uint64_t dAlo = mk_desc(dsm_u + SM_ALO);
    uint64_t dB   = mk_desc(dsm_u + SM_B);

    // ---- phase A1: Ahi*Bhi (mean-lo may still be streaming) ----
    asm volatile("cp.async.wait_group 1;" ::: "memory");
    __syncthreads();
    if (tid == 0) {
        asm volatile("fence.proxy.async.shared::cta;" ::: "memory");
        #pragma unroll
        for (int t = 0; t < 16; t++)
            mma_bf16_ss(tmem, dAhi + koff(t), dB + koff(t), t > 0);
    }
    // ---- phase A2: Alo*Bhi ----
    asm volatile("cp.async.wait_group 0;" ::: "memory");
    __syncthreads();
    if (tid == 0) {
        asm volatile("fence.proxy.async.shared::cta;" ::: "memory");
        #pragma unroll
        for (int t = 0; t < 16; t++)
            mma_bf16_ss(tmem, dAlo + koff(t), dB + koff(t), 1);
        asm volatile(
            "tcgen05.commit.cta_group::1.mbarrier::arrive::one.shared::cluster.b64 [%0];"
            :: "r"(mbar_a) : "memory");
    }

    // ---- preload Blo into registers under the phase-A shadow ----
    uint4 bl[16];
    #pragma unroll
    for (int it = 0; it < 16; it++)
        bl[it] = *(const uint4*)(Blo + rr[it] * 256 + cc[it]);

    // Layer 2: re-zero g_deg for the next call here, in the MMA shadow (agg2 was
    // the last reader; this kernel is stream-ordered after it). Grid covers NN.
    if (LAYER == 2) {
        int zi = blockIdx.x * 256 + tid;
        if (zi < NN) g_deg[zi] = 0;
    }

    mbar_wait(mbar_a, 0);

    // ---- swap B -> Blo (STS only) ----
    #pragma unroll
    for (int it = 0; it < 16; it++)
        *(uint4*)(dsm + SM_B + so[it]) = bl[it];
    __syncthreads();

    // ---- phase B: Ahi*Blo ----
    if (tid == 0) {
        asm volatile("fence.proxy.async.shared::cta;" ::: "memory");
        #pragma unroll
        for (int t = 0; t < 16; t++)
            mma_bf16_ss(tmem, dAhi + koff(t), dB + koff(t), 1);
        asm volatile(
            "tcgen05.commit.cta_group::1.mbarrier::arrive::one.shared::cluster.b64 [%0];"
            :: "r"(mbar_a) : "memory");
    }
    mbar_wait(mbar_a, 1);
    asm volatile("tcgen05.fence::after_thread_sync;" ::: "memory");

    // ---- epilogue: warp w -> rows (w&3)*32+lane, cols (w>>2)*64..+63 ----
    const int sub = wid & 3, half = wid >> 2;
    const int cb = half * 64;
    uint32_t dr[64];
    #define LD32(p, a) \
        asm volatile("tcgen05.ld.sync.aligned.32x32b.x32.b32 " \
            "{%0,%1,%2,%3,%4,%5,%6,%7,%8,%9,%10,%11,%12,%13,%14,%15," \
            "%16,%17,%18,%19,%20,%21,%22,%23,%24,%25,%26,%27,%28,%29,%30,%31}, [%32];" \
            : "=r"((p)[0]),"=r"((p)[1]),"=r"((p)[2]),"=r"((p)[3]),"=r"((p)[4]),"=r"((p)[5]), \
              "=r"((p)[6]),"=r"((p)[7]),"=r"((p)[8]),"=r"((p)[9]),"=r"((p)[10]),"=r"((p)[11]), \
              "=r"((p)[12]),"=r"((p)[13]),"=r"((p)[14]),"=r"((p)[15]),"=r"((p)[16]),"=r"((p)[17]), \
              "=r"((p)[18]),"=r"((p)[19]),"=r"((p)[20]),"=r"((p)[21]),"=r"((p)[22]),"=r"((p)[23]), \
              "=r"((p)[24]),"=r"((p)[25]),"=r"((p)[26]),"=r"((p)[27]),"=r"((p)[28]),"=r"((p)[29]), \
              "=r"((p)[30]),"=r"((p)[31]) : "r"(a))
    LD32(dr,      tmem + cb);
    LD32(dr + 32, tmem + cb + 32);
    asm volatile("tcgen05.wait::ld.sync.aligned;" ::: "memory");
    #undef LD32

    const int r = sub * 32 + lane;          // local row
    const int gr = row0 + r;
    float v[64];
    float s = 0.f, sq = 0.f;
    #pragma unroll
    for (int j = 0; j < 64; j++) {
        float f = fmaxf(__uint_as_float(dr[j]) + sb[cb + j], 0.f);
        v[j] = f;
        s += f; sq += f * f;
    }

    if (LAYER == 1) {
        if (gr < NN) {
            size_t rbase = (size_t)gr * DD + cb;
            #pragma unroll
            for (int c4 = 0; c4 < 16; c4++)
                *(float4*)(g_h1 + rbase + c4 * 4) =
                    make_float4(v[c4*4+0], v[c4*4+1], v[c4*4+2], v[c4*4+3]);
        }
    } else {
        psS[half][r] = s;
        psQ[half][r] = sq;
        __syncthreads();
        float st = psS[0][r] + psS[1][r];
        float qt = psQ[0][r] + psQ[1][r];
        float mu  = st * (1.0f / DD);
        float var = qt * (1.0f / DD) - mu * mu;
        float rs  = rsqrtf(var + 1e-5f);
        if (gr < NN) {
            size_t rbase = (size_t)gr * DD + cb;
            #pragma unroll
            for (int c4 = 0; c4 < 16; c4++) {
                float4 o;
                o.x = (v[c4*4+0] - mu) * rs * slw[cb+c4*4+0] + slb[cb+c4*4+0];
                o.y = (v[c4*4+1] - mu) * rs * slw[cb+c4*4+1] + slb[cb+c4*4+1];
                o.z = (v[c4*4+2] - mu) * rs * slw[cb+c4*4+2] + slb[cb+c4*4+2];
                o.w = (v[c4*4+3] - mu) * rs * slw[cb+c4*4+3] + slb[cb+c4*4+3];
                *(float4*)(outp + rbase + c4 * 4) = o;
            }
        }
    }

    __syncthreads();
    if (tid == 0)
        asm volatile("mbarrier.inval.shared.b64 [%0];" :: "r"(mbar_a) : "memory");
    __syncthreads();
    if (wid == 0) {
        asm volatile("tcgen05.dealloc.cta_group::1.sync.aligned.b32 %0, %1;"
                     :: "r"(tmem), "r"(128u));
        asm volatile("tcgen05.relinquish_alloc_permit.cta_group::1.sync.aligned;");
    }
#endif  // TC5
}

// ---------------- launch ----------------
extern "C" void kernel_launch(void* const* d_in, const int* in_sizes, int n_in,
                              void* d_out, int out_size) {
    const float* x   = (const float*)d_in[0];
    const void*  ei  = d_in[1];
    const float* W1l = (const float*)d_in[2];
    const float* b1l = (const float*)d_in[3];
    const float* W1r = (const float*)d_in[4];
    const float* W2l = (const float*)d_in[5];
    const float* b2l = (const float*)d_in[6];
    const float* W2r = (const float*)d_in[7];
    const float* lnw = (const float*)d_in[8];
    const float* lnb = (const float*)d_in[9];
    float* out = (float*)d_out;

    cudaFuncSetAttribute(k_mma<1>, cudaFuncAttributeMaxDynamicSharedMemorySize, DSMEM);
    cudaFuncSetAttribute(k_mma<2>, cudaFuncAttributeMaxDynamicSharedMemorySize, DSMEM);

    const int ph_blocks  = WPREP_BLOCKS + HIST_BLOCKS;
    const int mma_blocks = (NN + 127) / 128;                    // 391

    // single-pass adjacency build (slot table, no CSR)
    k_ph<<<ph_blocks, 256>>>(ei, W1l, W1r, W2l, W2r);

    // layer 1
    k_agg<1><<<(NN * 32 + 255) / 256, 256>>>(x);
    k_mma<1><<<mma_blocks, 256, DSMEM>>>(x, b1l, nullptr, nullptr, out);

    // layer 2 (+ LayerNorm; re-zeros g_deg for next call)
    k_agg<2><<<(NN * 32 + 255) / 256, 256>>>(x);
    k_mma<2><<<mma_blocks, 256, DSMEM>>>(x, b2l, lnw, lnb, out);
}

// round 15
// speedup vs baseline: 1.3108x; 1.0138x over previous
#include <cuda_runtime.h>
#include <cuda_bf16.h>
#include <cstdint>

#define NN 50000
#define NE 800000
#define DD 128
#define MAXDEG 128   // Poisson(16) max over 50k nodes ~45; 128 is overwhelmingly safe
#define GRID_MMA 148
#define NTILES ((NN + 127) / 128)   // 391

// tcgen05 is only legal on arch-specific targets (sm_103a / sm_100a).
// The harness also compiles a plain compute_103 pass -> give it a stub body.
#if !defined(__CUDA_ARCH__) || defined(__CUDA_ARCH_FEAT_SM103_ALL) || \
    defined(__CUDA_ARCH_FEAT_SM100_ALL) || defined(__CUDA_ARCH_SPECIFIC__)
#define TC5 1
#else
#define TC5 0
#endif

// ---------------- scratch (no allocs -> device globals) ----------------
// g_deg must be 0 at entry to k_ph: static-init covers call 1; k_mma<2> re-zeros
// every call (agg2 is the last reader), keeping the invariant across replays.
__device__ int   g_deg[NN];
__device__ int   g_adj[(size_t)NN * MAXDEG];   // slot table: adj[dst*128 + rank]
__device__ __align__(16) float          g_h1[(size_t)NN * DD];   // fp32 (split at mma load)
__device__ __align__(16) __nv_bfloat16  g_mhi[(size_t)NN * DD];
__device__ __align__(16) __nv_bfloat16  g_mlo[(size_t)NN * DD];
__device__ __align__(16) __nv_bfloat16  g_B1hi[DD * 2 * DD];  // [j][k] k-major, K=256
__device__ __align__(16) __nv_bfloat16  g_B1lo[DD * 2 * DD];
__device__ __align__(16) __nv_bfloat16  g_B2hi[DD * 2 * DD];
__device__ __align__(16) __nv_bfloat16  g_B2lo[DD * 2 * DD];

// ---------------- small helpers ----------------
__device__ __forceinline__ uint32_t s2u32(const void* p) {
    uint32_t a;
    asm("{ .reg .u64 t; cvta.to.shared.u64 t, %1; cvt.u32.u64 %0, t; }" : "=r"(a) : "l"(p));
    return a;
}
__device__ __forceinline__ unsigned pk2(__nv_bfloat16 a, __nv_bfloat16 b) {
    unsigned short ua = *(unsigned short*)&a, ub = *(unsigned short*)&b;
    return (unsigned)ua | ((unsigned)ub << 16);
}
__device__ __forceinline__ void split1(float v, __nv_bfloat16& h, __nv_bfloat16& l) {
    h = __float2bfloat16_rn(v);
    l = __float2bfloat16_rn(v - __bfloat162float(h));
}

// ---------------- fused: weight split | slot-table build (one pass, no CSR) ----------------
#define WPREP_BLOCKS 128
#define HIST_BLOCKS  ((NE + 255) / 256)                // 3125
__global__ void k_ph(const void* __restrict__ ei,
                     const float* __restrict__ W1l, const float* __restrict__ W1r,
                     const float* __restrict__ W2l, const float* __restrict__ W2r) {
    int b = blockIdx.x;
    if (b < WPREP_BLOCKS) {
        int id = b * 256 + threadIdx.x;  // < 32768
        int j = id >> 8, k = id & 255;
        float w1 = (k < DD) ? W1l[j * DD + k] : W1r[j * DD + k - DD];
        float w2 = (k < DD) ? W2l[j * DD + k] : W2r[j * DD + k - DD];
        __nv_bfloat16 h, l;
        split1(w1, h, l); g_B1hi[id] = h; g_B1lo[id] = l;
        split1(w2, h, l); g_B2hi[id] = h; g_B2lo[id] = l;
    } else {
        // local edge-dtype detect (JAX x64-off -> int32 likely).
        const unsigned long long* e64 = (const unsigned long long*)ei;
        bool is32 = false;
        #pragma unroll
        for (int k = 0; k < 8; k++)
            if (e64[k] >= (unsigned long long)NN) is32 = true;
        int e = (b - WPREP_BLOCKS) * 256 + threadIdx.x;
        if (e < NE) {
            int dst = is32 ? ((const int*)ei)[NE + e] : (int)((const long long*)ei)[NE + e];
            int src = is32 ? ((const int*)ei)[e]      : (int)((const long long*)ei)[e];
            if ((unsigned)dst < (unsigned)NN && (unsigned)src < (unsigned)NN) {
                int r = atomicAdd(&g_deg[dst], 1);
                if (r < MAXDEG) g_adj[(size_t)dst * MAXDEG + r] = src;
            }
        }
    }
}

// ---------------- mean aggregation: one warp per node; fp32 in, bf16 hi/lo out ----------------
// R12/R14 form: unroll-4, 2 f32x2 chains, regs=32, occ~84%. AT the chip L2 cap.
template <int LAYER>
__global__ void __launch_bounds__(256) k_agg(const float* __restrict__ x) {
    const float* feat = (LAYER == 1) ? x : (const float*)g_h1;
    int warp = (blockIdx.x * blockDim.x + threadIdx.x) >> 5;
    int lane = threadIdx.x & 31;
    if (warp >= NN) return;
    const int* adjrow = g_adj + (size_t)warp * MAXDEG;
    int d = min(g_deg[warp], MAXDEG);
    unsigned long long a01 = 0ULL, a23 = 0ULL;
    for (int b = 0; b < d; b += 32) {
        int m  = min(32, d - b);
        int sl = (lane < m) ? adjrow[b + lane] : 0;
        #pragma unroll 4
        for (int j = 0; j < m; j++) {
            int s = __shfl_sync(0xffffffffu, sl, j);
            const ulonglong2 v = __ldg((const ulonglong2*)(feat + (size_t)s * DD) + lane);
            asm("add.rn.f32x2 %0, %0, %1;" : "+l"(a01) : "l"(v.x));
            asm("add.rn.f32x2 %0, %0, %1;" : "+l"(a23) : "l"(v.y));
        }
    }
    float inv = 1.0f / (float)max(d, 1);
    float f0, f1, f2, f3;
    asm("mov.b64 {%0, %1}, %2;" : "=f"(f0), "=f"(f1) : "l"(a01));
    asm("mov.b64 {%0, %1}, %2;" : "=f"(f2), "=f"(f3) : "l"(a23));
    f0 *= inv; f1 *= inv; f2 *= inv; f3 *= inv;
    __nv_bfloat16 h0, h1, h2, h3, l0, l1, l2, l3;
    split1(f0, h0, l0); split1(f1, h1, l1);
    split1(f2, h2, l2); split1(f3, h3, l3);
    size_t rb = (size_t)warp * DD;
    ((uint2*)(g_mhi + rb))[lane] = make_uint2(pk2(h0, h1), pk2(h2, h3));
    ((uint2*)(g_mlo + rb))[lane] = make_uint2(pk2(l0, l1), pk2(l2, l3));
}

// ================= persistent tcgen05 GEMM =================
// Grid 148. Each CTA loops tiles (stride 148). Bhi resident in smem (loaded once),
// Blo resident in REGISTERS (16 x uint4), phase-B reads Blo from the dead Alo
// buffer. Per tile only A streams. D = Ahi*Bhi + Alo*Bhi + Ahi*Blo.

#define SM_AHI 0
#define SM_ALO 65536
#define SM_B   131072
#define DSMEM  (196608 + 1024)

static constexpr uint32_t IDESC_BF16 =
    (1u << 4) | (1u << 7) | (1u << 10) | ((128u / 8) << 17) | ((128u / 16) << 24);

// blocked SW128 atom layout: atom = 8 rows x 64 bf16 (1024B); 16 atom-rows, 4 atom-cols
__device__ __forceinline__ int sw_chunk(int row, int col) {   // col multiple of 8
    int byte = ((row >> 3) + (col >> 6) * 16) * 1024 + (row & 7) * 128 + (col & 63) * 2;
    return byte ^ ((byte >> 3) & 0x70);
}
__device__ __forceinline__ uint64_t mk_desc(uint32_t addr) {
    const uint64_t base = (2ull << 61) | (1ull << 46) | (64ull << 32) | (1ull << 16);
    return base | ((uint64_t)(addr >> 4) & 0x3FFF);
}
__device__ __forceinline__ uint64_t koff(int t) {   // K16-step t=0..15
    return (uint64_t)(((t >> 2) * 1024) + (t & 3) * 2);
}

#if TC5
__device__ __forceinline__ void mma_bf16_ss(uint32_t d, uint64_t ad, uint64_t bd,
                                            uint32_t en) {
    asm volatile(
        "{\n\t.reg .pred p;\n\tsetp.ne.u32 p, %4, 0;\n\t"
        "tcgen05.mma.cta_group::1.kind::f16 [%0], %1, %2, %3, {%5, %5, %5, %5}, p;\n\t}"
        :: "r"(d), "l"(ad), "l"(bd), "r"(IDESC_BF16), "r"(en), "r"(0u) : "memory");
}
__device__ __forceinline__ void cp16(uint32_t saddr, const void* gaddr) {
    asm volatile("cp.async.cg.shared.global [%0], [%1], 16;"
                 :: "r"(saddr), "l"(gaddr) : "memory");
}
#endif
__device__ __forceinline__ void mbar_wait(uint32_t mbar, uint32_t parity) {
    uint32_t done;
    asm volatile(
        "{\n\t.reg .pred p;\n\t"
        "mbarrier.try_wait.parity.acquire.cta.shared::cta.b64 p, [%1], %2;\n\t"
        "selp.b32 %0, 1, 0, p;\n\t}"
        : "=r"(done) : "r"(mbar), "r"(parity) : "memory");
    if (!done) {
        asm volatile(
            "{\n\t.reg .pred P1;\n\t"
            "WL_%=:\n\t"
            "mbarrier.try_wait.parity.acquire.cta.shared::cta.b64 P1, [%0], %1, 0x989680;\n\t"
            "@P1 bra.uni WD_%=;\n\t"
            "bra.uni WL_%=;\n\t"
            "WD_%=:\n\t}"
            :: "r"(mbar), "r"(parity) : "memory");
    }
}

template <int LAYER>
__global__ void __launch_bounds__(256) k_mma(
    const float* __restrict__ xin, const float* __restrict__ bias,
    const float* __restrict__ lnw, const float* __restrict__ lnb,
    float* __restrict__ outp)
{
#if TC5
    extern __shared__ char dsm_raw[];
    __shared__ uint32_t s_tmem;
    __shared__ __align__(8) unsigned long long s_mbar;
    __shared__ float sb[DD], slw[DD], slb[DD];
    __shared__ float psS[2][DD], psQ[2][DD];

    const uint32_t raw_u = s2u32(dsm_raw);
    const uint32_t dsm_u = (raw_u + 1023u) & ~1023u;   // SW128 needs 1KB-aligned base
    char* dsm = dsm_raw + (dsm_u - raw_u);

    const int tid  = threadIdx.x;
    const int wid  = tid >> 5;
    const int lane = tid & 31;

    const float* hsrc = (LAYER == 1) ? xin : (const float*)g_h1;
    const __nv_bfloat16* Bhi = (LAYER == 1) ? g_B1hi : g_B2hi;
    const __nv_bfloat16* Blo = (LAYER == 1) ? g_B1lo : g_B2lo;

    uint32_t mbar_a = s2u32(&s_mbar);
    uint32_t tmslot = s2u32(&s_tmem);

    if (wid == 0) {
        asm volatile(
            "tcgen05.alloc.cta_group::1.sync.aligned.shared::cta.b32 [%0], %1;"
            :: "r"(tmslot), "r"(128u) : "memory");
    }
    if (tid == 0)
        asm volatile("mbarrier.init.shared.b64 [%0], %1;" :: "r"(mbar_a), "r"(1u) : "memory");
    if (tid < DD) {
        sb[tid] = bias[tid];
        if (LAYER == 2) { slw[tid] = lnw[tid]; slb[tid] = lnb[tid]; }
    }

    // ---- Bhi -> smem (once), group 0 ----
    #pragma unroll
    for (int it = 0; it < 16; it++) {
        int c = tid + it * 256;
        int r = c >> 5, col = (c & 31) * 8;
        cp16(dsm_u + SM_B + sw_chunk(r, col), Bhi + r * 256 + col);
    }
    asm volatile("cp.async.commit_group;" ::: "memory");

    // ---- Blo -> registers (resident across tiles) ----
    uint4 bl[16];
    #pragma unroll
    for (int it = 0; it < 16; it++) {
        int c = tid + it * 256;
        int r = c >> 5, col = (c & 31) * 8;
        bl[it] = *(const uint4*)(Blo + r * 256 + col);
    }

    // Layer 2: re-zero g_deg for the next call (agg2 already consumed it).
    if (LAYER == 2) {
        for (int zi = blockIdx.x * 256 + tid; zi < NN; zi += GRID_MMA * 256)
            g_deg[zi] = 0;
    }

    __syncthreads();   // alloc + mbar init visible
    uint32_t tmem;
    asm volatile("ld.shared.b32 %0, [%1];" : "=r"(tmem) : "r"(tmslot));

    const uint64_t dAhi = mk_desc(dsm_u + SM_AHI);
    const uint64_t dAlo = mk_desc(dsm_u + SM_ALO);
    const uint64_t dB   = mk_desc(dsm_u + SM_B);

    int p = 0;   // mbar parity counter

    for (int tile = blockIdx.x; tile < NTILES; tile += GRID_MMA) {
        const int row0 = tile * 128;

        // A loads: mean-hi group, mean-lo group (left half), fp32 right half sync
        #pragma unroll
        for (int it = 0; it < 16; it++) {
            int c = tid + it * 256;
            int r = c >> 5, col = (c & 31) * 8;
            if (col < DD) {
                int gr = row0 + r; if (gr >= NN) gr = 0;   // clamp: rows never stored
                cp16(dsm_u + SM_AHI + sw_chunk(r, col), g_mhi + (size_t)gr * DD + col);
            }
        }
        asm volatile("cp.async.commit_group;" ::: "memory");   // group: Ahi
        #pragma unroll
        for (int it = 0; it < 16; it++) {
            int c = tid + it * 256;
            int r = c >> 5, col = (c & 31) * 8;
            if (col < DD) {
                int gr = row0 + r; if (gr >= NN) gr = 0;
                cp16(dsm_u + SM_ALO + sw_chunk(r, col), g_mlo + (size_t)gr * DD + col);
            }
        }
        asm volatile("cp.async.commit_group;" ::: "memory");   // group: Alo

        #pragma unroll
        for (int it = 0; it < 16; it++) {
            int c = tid + it * 256;
            int r = c >> 5, col = (c & 31) * 8;
            if (col >= DD) {
                int gr = row0 + r; if (gr >= NN) gr = 0;
                const float* xr = hsrc + (size_t)gr * DD + (col - DD);
                float4 a = *(const float4*)xr;
                float4 b = *(const float4*)(xr + 4);
                __nv_bfloat16 h[8], l[8];
                split1(a.x, h[0], l[0]); split1(a.y, h[1], l[1]);
                split1(a.z, h[2], l[2]); split1(a.w, h[3], l[3]);
                split1(b.x, h[4], l[4]); split1(b.y, h[5], l[5]);
                split1(b.z, h[6], l[6]); split1(b.w, h[7], l[7]);
                int so = sw_chunk(r, col);
                *(uint4*)(dsm + SM_AHI + so) =
                    make_uint4(pk2(h[0],h[1]), pk2(h[2],h[3]), pk2(h[4],h[5]), pk2(h[6],h[7]));
                *(uint4*)(dsm + SM_ALO + so) =
                    make_uint4(pk2(l[0],l[1]), pk2(l[2],l[3]), pk2(l[4],l[5]), pk2(l[6],l[7]));
            }
        }

        // phase A1: Ahi*Bhi (Alo may still stream)
        asm volatile("cp.async.wait_group 1;" ::: "memory");
        __syncthreads();
        if (tid == 0) {
            asm volatile("fence.proxy.async.shared::cta;" ::: "memory");
            #pragma unroll
            for (int t = 0; t < 16; t++)
                mma_bf16_ss(tmem, dAhi + koff(t), dB + koff(t), t > 0);
        }
        // phase A2: Alo*Bhi
        asm volatile("cp.async.wait_group 0;" ::: "memory");
        __syncthreads();
        if (tid == 0) {
            asm volatile("fence.proxy.async.shared::cta;" ::: "memory");
            #pragma unroll
            for (int t = 0; t < 16; t++)
                mma_bf16_ss(tmem, dAlo + koff(t), dB + koff(t), 1);
            asm volatile(
                "tcgen05.commit.cta_group::1.mbarrier::arrive::one.shared::cluster.b64 [%0];"
                :: "r"(mbar_a) : "memory");
        }
        mbar_wait(mbar_a, p & 1); p++;

        // Blo -> dead Alo buffer (Bhi smem stays resident)
        #pragma unroll
        for (int it = 0; it < 16; it++) {
            int c = tid + it * 256;
            int r = c >> 5, col = (c & 31) * 8;
            *(uint4*)(dsm + SM_ALO + sw_chunk(r, col)) = bl[it];
        }
        __syncthreads();

        // phase B: Ahi*Blo (Blo lives in the Alo buffer)
        if (tid == 0) {
            asm volatile("fence.proxy.async.shared::cta;" ::: "memory");
            #pragma unroll
            for (int t = 0; t < 16; t++)
                mma_bf16_ss(tmem, dAhi + koff(t), dAlo + koff(t), 1);
            asm volatile(
                "tcgen05.commit.cta_group::1.mbarrier::arrive::one.shared::cluster.b64 [%0];"
                :: "r"(mbar_a) : "memory");
        }
        mbar_wait(mbar_a, p & 1); p++;
        asm volatile("tcgen05.fence::after_thread_sync;" ::: "memory");

        // epilogue: warp w -> rows (w&3)*32+lane, cols (w>>2)*64..+63
        const int sub = wid & 3, half = wid >> 2;
        const int cb = half * 64;
        uint32_t dr[64];
        #define LD32(ptr, a) \
            asm volatile("tcgen05.ld.sync.aligned.32x32b.x32.b32 " \
                "{%0,%1,%2,%3,%4,%5,%6,%7,%8,%9,%10,%11,%12,%13,%14,%15," \
                "%16,%17,%18,%19,%20,%21,%22,%23,%24,%25,%26,%27,%28,%29,%30,%31}, [%32];" \
                : "=r"((ptr)[0]),"=r"((ptr)[1]),"=r"((ptr)[2]),"=r"((ptr)[3]), \
                  "=r"((ptr)[4]),"=r"((ptr)[5]),"=r"((ptr)[6]),"=r"((ptr)[7]), \
                  "=r"((ptr)[8]),"=r"((ptr)[9]),"=r"((ptr)[10]),"=r"((ptr)[11]), \
                  "=r"((ptr)[12]),"=r"((ptr)[13]),"=r"((ptr)[14]),"=r"((ptr)[15]), \
                  "=r"((ptr)[16]),"=r"((ptr)[17]),"=r"((ptr)[18]),"=r"((ptr)[19]), \
                  "=r"((ptr)[20]),"=r"((ptr)[21]),"=r"((ptr)[22]),"=r"((ptr)[23]), \
                  "=r"((ptr)[24]),"=r"((ptr)[25]),"=r"((ptr)[26]),"=r"((ptr)[27]), \
                  "=r"((ptr)[28]),"=r"((ptr)[29]),"=r"((ptr)[30]),"=r"((ptr)[31]) : "r"(a))
        LD32(dr,      tmem + cb);
        LD32(dr + 32, tmem + cb + 32);
        asm volatile("tcgen05.wait::ld.sync.aligned;" ::: "memory");
        #undef LD32

        const int r = sub * 32 + lane;
        const int gr = row0 + r;
        float v[64];
        float s = 0.f, sq = 0.f;
        #pragma unroll
        for (int j = 0; j < 64; j++) {
            float f = fmaxf(__uint_as_float(dr[j]) + sb[cb + j], 0.f);
            v[j] = f;
            s += f; sq += f * f;
        }

        if (LAYER == 1) {
            if (gr < NN) {
                size_t rbase = (size_t)gr * DD + cb;
                #pragma unroll
                for (int c4 = 0; c4 < 16; c4++)
                    *(float4*)(g_h1 + rbase + c4 * 4) =
                        make_float4(v[c4*4+0], v[c4*4+1], v[c4*4+2], v[c4*4+3]);
            }
        } else {
            psS[half][r] = s;
            psQ[half][r] = sq;
            __syncthreads();
            float st = psS[0][r] + psS[1][r];
            float qt = psQ[0][r] + psQ[1][r];
            float mu  = st * (1.0f / DD);
            float var = qt * (1.0f / DD) - mu * mu;
            float rs  = rsqrtf(var + 1e-5f);
            if (gr < NN) {
                size_t rbase = (size_t)gr * DD + cb;
                #pragma unroll
                for (int c4 = 0; c4 < 16; c4++) {
                    float4 o;
                    o.x = (v[c4*4+0] - mu) * rs * slw[cb+c4*4+0] + slb[cb+c4*4+0];
                    o.y = (v[c4*4+1] - mu) * rs * slw[cb+c4*4+1] + slb[cb+c4*4+1];
                    o.z = (v[c4*4+2] - mu) * rs * slw[cb+c4*4+2] + slb[cb+c4*4+2];
                    o.w = (v[c4*4+3] - mu) * rs * slw[cb+c4*4+3] + slb[cb+c4*4+3];
                    *(float4*)(outp + rbase + c4 * 4) = o;
                }
            }
        }
        __syncthreads();   // epilogue smem (psS/psQ) + A buffers free for next tile
    }

    if (tid == 0)
        asm volatile("mbarrier.inval.shared.b64 [%0];" :: "r"(mbar_a) : "memory");
    __syncthreads();
    if (wid == 0) {
        asm volatile("tcgen05.dealloc.cta_group::1.sync.aligned.b32 %0, %1;"
                     :: "r"(tmem), "r"(128u));
        asm volatile("tcgen05.relinquish_alloc_permit.cta_group::1.sync.aligned;");
    }
#endif  // TC5
}

// ---------------- launch ----------------
extern "C" void kernel_launch(void* const* d_in, const int* in_sizes, int n_in,
                              void* d_out, int out_size) {
    const float* x   = (const float*)d_in[0];
    const void*  ei  = d_in[1];
    const float* W1l = (const float*)d_in[2];
    const float* b1l = (const float*)d_in[3];
    const float* W1r = (const float*)d_in[4];
    const float* W2l = (const float*)d_in[5];
    const float* b2l = (const float*)d_in[6];
    const float* W2r = (const float*)d_in[7];
    const float* lnw = (const float*)d_in[8];
    const float* lnb = (const float*)d_in[9];
    float* out = (float*)d_out;

    cudaFuncSetAttribute(k_mma<1>, cudaFuncAttributeMaxDynamicSharedMemorySize, DSMEM);
    cudaFuncSetAttribute(k_mma<2>, cudaFuncAttributeMaxDynamicSharedMemorySize, DSMEM);

    const int ph_blocks = WPREP_BLOCKS + HIST_BLOCKS;

    // single-pass adjacency build (slot table, no CSR)
    k_ph<<<ph_blocks, 256>>>(ei, W1l, W1r, W2l, W2r);

    // layer 1
    k_agg<1><<<(NN * 32 + 255) / 256, 256>>>(x);
    k_mma<1><<<GRID_MMA, 256, DSMEM>>>(x, b1l, nullptr, nullptr, out);

    // layer 2 (+ LayerNorm; re-zeros g_deg for next call)
    k_agg<2><<<(NN * 32 + 255) / 256, 256>>>(x);
    k_mma<2><<<GRID_MMA, 256, DSMEM>>>(x, b2l, lnw, lnb, out);
}